// round 7
// baseline (speedup 1.0000x reference)
#include <cuda_runtime.h>
#include <cuda_bf16.h>
#include <cstdint>

// Fused 3D windowed attention block — mma.sync bf16 3-split GEMMs + scalar fp32 attention.
// R7: 2m x 4n warp tiling, ldsm x4 for B, pre-split weights in __device__ bufs + cp.async fills.
// One CTA per 4x4x4 window (4096 CTAs, 256 threads = 8 warps).

#define D0 30
#define H0 62
#define W0 126
#define MTOT (30*62*126)

#define AST 136            // halves per row, A tiles (64 rows)
#define BST 136            // halves per row, B tiles (128 rows)
#define QS_STRIDE 388

// byte offsets in dynamic smem
#define SM_AHI 0
#define SM_ALO (SM_AHI + 64*AST*2)       // 17408
#define SM_BHI (SM_ALO + 64*AST*2)       // 34816
#define SM_BLO (SM_BHI + 128*BST*2)      // 69632
#define SM_QS  (SM_BLO + 128*BST*2)      // 104448
#define SMEM_BYTES (SM_QS + 64*QS_STRIDE*4)   // 203776

// pre-split weight tiles: [mat 0..3][n 128][k 128] halves (mats: q,k,v,conv)
__device__ __align__(256) __nv_bfloat16 g_whi[4 * 128 * 128];
__device__ __align__(256) __nv_bfloat16 g_wlo[4 * 128 * 128];

__device__ __forceinline__ uint32_t smem_u32(const void* p) {
    uint32_t a;
    asm("{ .reg .u64 t; cvta.to.shared.u64 t, %1; cvt.u32.u64 %0, t; }"
        : "=r"(a) : "l"(p));
    return a;
}
__device__ __forceinline__ void ldsm4(uint32_t (&r)[4], uint32_t addr) {
    asm volatile("ldmatrix.sync.aligned.m8n8.x4.shared.b16 {%0,%1,%2,%3}, [%4];"
                 : "=r"(r[0]), "=r"(r[1]), "=r"(r[2]), "=r"(r[3]) : "r"(addr));
}
__device__ __forceinline__ void mma16816(float (&d)[4], const uint32_t (&a)[4],
                                         uint32_t b0, uint32_t b1) {
    asm volatile("mma.sync.aligned.m16n8k16.row.col.f32.bf16.bf16.f32 "
                 "{%0,%1,%2,%3}, {%4,%5,%6,%7}, {%8,%9}, {%0,%1,%2,%3};"
                 : "+f"(d[0]), "+f"(d[1]), "+f"(d[2]), "+f"(d[3])
                 : "r"(a[0]), "r"(a[1]), "r"(a[2]), "r"(a[3]),
                   "r"(b0), "r"(b1));
}
__device__ __forceinline__ void cp_async16(uint32_t saddr, const void* gaddr) {
    asm volatile("cp.async.cg.shared.global [%0], [%1], 16;"
                 :: "r"(saddr), "l"(gaddr));
}
#define CP_COMMIT() asm volatile("cp.async.commit_group;" ::: "memory")
#define CP_WAIT0()  asm volatile("cp.async.wait_group 0;" ::: "memory")

// store (v0,v1) as bf16 hi + residual lo at (row, col..col+1)
__device__ __forceinline__ void split_pair(char* hiB, char* loB, int row, int col,
                                           int stride, float v0, float v1) {
    __nv_bfloat16 h0 = __float2bfloat16(v0);
    __nv_bfloat16 h1 = __float2bfloat16(v1);
    __nv_bfloat16 l0 = __float2bfloat16(v0 - __bfloat162float(h0));
    __nv_bfloat16 l1 = __float2bfloat16(v1 - __bfloat162float(h1));
    int off = (row * stride + col) * 2;
    *(__nv_bfloat162*)(hiB + off) = __halves2bfloat162(h0, h1);
    *(__nv_bfloat162*)(loB + off) = __halves2bfloat162(l0, l1);
}

// fill B hi/lo tiles from pre-split gmem via cp.async (16 x 16B per thread)
__device__ __forceinline__ void fillB_async(int mat, uint32_t sb, int t) {
    const __nv_bfloat16* gh = g_whi + mat * 16384;
    const __nv_bfloat16* gl = g_wlo + mat * 16384;
    #pragma unroll
    for (int it = 0; it < 8; ++it) {
        int id = t + 256 * it;       // 0..2047
        int n = id >> 4, c = id & 15;
        uint32_t so = (uint32_t)((n * BST + c * 8) * 2);
        const int go = n * 128 + c * 8;
        cp_async16(sb + SM_BHI + so, gh + go);
        cp_async16(sb + SM_BLO + so, gl + go);
    }
}

// 64x128x128 GEMM pass, warp tile 2m x 4n, 3-split bf16
__device__ __forceinline__ void mma_block(uint32_t aHi, uint32_t aLo,
                                          uint32_t bHi, uint32_t bLo,
                                          int lane, int wm, int wn,
                                          float acc[2][4][4]) {
    const int r8 = lane & 7, g = lane >> 3;
    const uint32_t aoff = (uint32_t)(((wm * 32 + r8 + 8 * (g & 1)) * AST + 8 * (g >> 1)) * 2);
    const uint32_t boff = (uint32_t)(((wn * 32 + r8 + 8 * ((lane >> 4) & 1)) * BST
                                      + 8 * ((lane >> 3) & 1)) * 2);
    #pragma unroll
    for (int kk = 0; kk < 8; ++kk) {
        uint32_t ah[2][4], al[2][4], bh[2][4], bl[2][4];
        #pragma unroll
        for (int mt = 0; mt < 2; ++mt) {
            uint32_t o = aoff + (uint32_t)((mt * 16 * AST + kk * 16) * 2);
            ldsm4(ah[mt], aHi + o);
            ldsm4(al[mt], aLo + o);
        }
        #pragma unroll
        for (int np = 0; np < 2; ++np) {
            uint32_t o = boff + (uint32_t)((np * 16 * BST + kk * 16) * 2);
            ldsm4(bh[np], bHi + o);
            ldsm4(bl[np], bLo + o);
        }
        #pragma unroll
        for (int mt = 0; mt < 2; ++mt)
            #pragma unroll
            for (int np = 0; np < 2; ++np)
                #pragma unroll
                for (int s = 0; s < 2; ++s) {
                    int nt = np * 2 + s;
                    mma16816(acc[mt][nt], ah[mt], bh[np][2 * s], bh[np][2 * s + 1]);
                    mma16816(acc[mt][nt], ah[mt], bl[np][2 * s], bl[np][2 * s + 1]);
                    mma16816(acc[mt][nt], al[mt], bh[np][2 * s], bh[np][2 * s + 1]);
                }
    }
}

__device__ __forceinline__ float dot4(float4 a, float4 b) {
    return fmaf(a.x, b.x, fmaf(a.y, b.y, fmaf(a.z, b.z, a.w * b.w)));
}

// ---------------- prep kernel: split weights into g_whi/g_wlo ----------------
__global__ void prep_weights(const float* __restrict__ qkv_w,
                             const float* __restrict__ conv_w)
{
    int t = blockIdx.x * 256 + threadIdx.x;   // 0..16383
    int base = t * 4;                          // float index, 0..65532
    const float* src = (base < 49152) ? (qkv_w + base) : (conv_w + (base - 49152));
    float4 v = *(const float4*)src;
    __nv_bfloat16 h0 = __float2bfloat16(v.x), h1 = __float2bfloat16(v.y);
    __nv_bfloat16 h2 = __float2bfloat16(v.z), h3 = __float2bfloat16(v.w);
    __nv_bfloat16 l0 = __float2bfloat16(v.x - __bfloat162float(h0));
    __nv_bfloat16 l1 = __float2bfloat16(v.y - __bfloat162float(h1));
    __nv_bfloat16 l2 = __float2bfloat16(v.z - __bfloat162float(h2));
    __nv_bfloat16 l3 = __float2bfloat16(v.w - __bfloat162float(h3));
    *(__nv_bfloat162*)(g_whi + base)     = __halves2bfloat162(h0, h1);
    *(__nv_bfloat162*)(g_whi + base + 2) = __halves2bfloat162(h2, h3);
    *(__nv_bfloat162*)(g_wlo + base)     = __halves2bfloat162(l0, l1);
    *(__nv_bfloat162*)(g_wlo + base + 2) = __halves2bfloat162(l2, l3);
}

// ---------------- main kernel ----------------
__global__ void __launch_bounds__(256, 1)
fused_window_attn_mma(const float* __restrict__ x,
                      const float* __restrict__ qkv_b,
                      const float* __restrict__ conv_b,
                      float* __restrict__ out)
{
    extern __shared__ char smemc[];
    const uint32_t sb = smem_u32(smemc);
    float* qsF = (float*)(smemc + SM_QS);

    const int t    = threadIdx.x;
    const int wid  = t >> 5;
    const int lane = t & 31;
    const int wi = blockIdx.x;
    const int bz = wi >> 9, by = (wi >> 5) & 15, bx = wi & 31;
    const int z0 = bz * 4, y0 = by * 4, x0 = bx * 4;

    // ---------------- phase 1: B chunk0 via cp.async; gather x -> A hi/lo ----
    fillB_async(0, sb, t);
    CP_COMMIT();

    #pragma unroll
    for (int it = 0; it < 16; ++it) {
        int idx = t + 256 * it;      // 0..4095
        int l  = idx & 63;
        int cp = idx >> 6;           // channel pair 0..63
        int gz = z0 + (l >> 4);
        int gy = y0 + ((l >> 2) & 3);
        int gx = x0 + (l & 3);
        float v0 = 0.f, v1 = 0.f;
        if (gz < D0 && gy < H0 && gx < W0) {
            size_t base = (size_t)(gz * H0 + gy) * W0 + gx;
            v0 = x[(size_t)(2 * cp) * MTOT + base];
            v1 = x[(size_t)(2 * cp + 1) * MTOT + base];
        }
        split_pair(smemc + SM_AHI, smemc + SM_ALO, l, 2 * cp, AST, v0, v1);
    }
    CP_WAIT0();
    __syncthreads();

    const uint32_t aHi = sb + SM_AHI, aLo = sb + SM_ALO;
    const uint32_t bHi = sb + SM_BHI, bLo = sb + SM_BLO;
    const int wm = wid >> 2;       // 0..1  (m half)
    const int wn = wid & 3;        // 0..3  (n quarter)

    // ---------------- phase 2: QKV GEMM, 3 chunks of N=128 ----------------
    #pragma unroll 1
    for (int chunk = 0; chunk < 3; ++chunk) {
        if (chunk > 0) {
            __syncthreads();   // all warps done with previous B
            fillB_async(chunk, sb, t);
            CP_COMMIT();
            CP_WAIT0();
            __syncthreads();
        }
        float acc[2][4][4];
        #pragma unroll
        for (int mt = 0; mt < 2; ++mt)
            #pragma unroll
            for (int nt = 0; nt < 4; ++nt)
                #pragma unroll
                for (int e = 0; e < 4; ++e) acc[mt][nt][e] = 0.f;

        mma_block(aHi, aLo, bHi, bLo, lane, wm, wn, acc);

        // epilogue: qs[row][chunk*128 + col] = acc + bias
        #pragma unroll
        for (int mt = 0; mt < 2; ++mt) {
            int row0 = wm * 32 + mt * 16 + (lane >> 2);
            #pragma unroll
            for (int nt = 0; nt < 4; ++nt) {
                int col = wn * 32 + nt * 8 + 2 * (lane & 3);
                float2 bv = *(const float2*)(qkv_b + chunk * 128 + col);
                *(float2*)(qsF + (size_t)row0 * QS_STRIDE + chunk * 128 + col) =
                    make_float2(acc[mt][nt][0] + bv.x, acc[mt][nt][1] + bv.y);
                *(float2*)(qsF + (size_t)(row0 + 8) * QS_STRIDE + chunk * 128 + col) =
                    make_float2(acc[mt][nt][2] + bv.x, acc[mt][nt][3] + bv.y);
            }
        }
    }
    __syncthreads();   // qs ready; A and B regions free

    // conv weights fill overlaps attention
    fillB_async(3, sb, t);
    CP_COMMIT();

    // ---------------- phase 3: attention (scalar fp32, warp = head) ----------
    unsigned long long pm = 0ull;
    if (bz == 7 || by == 15 || bx == 31) {
        #pragma unroll
        for (int m = 0; m < 64; ++m) {
            bool p = (bz == 7 && (m >> 4) >= 2) ||
                     (by == 15 && ((m >> 2) & 3) >= 2) ||
                     (bx == 31 && (m & 3) >= 2);
            pm |= (unsigned long long)(p ? 1u : 0u) << m;
        }
    }

    const int head = wid;
    const int r0 = lane, r1 = lane + 32;
    const unsigned p0 = (unsigned)(pm >> r0) & 1u;
    const unsigned p1 = (unsigned)(pm >> r1) & 1u;

    float4 q0[4], q1[4];
    {
        const float4* q0p = (const float4*)(qsF + (size_t)r0 * QS_STRIDE + head * 16);
        const float4* q1p = (const float4*)(qsF + (size_t)r1 * QS_STRIDE + head * 16);
        #pragma unroll
        for (int i = 0; i < 4; ++i) { q0[i] = q0p[i]; q1[i] = q1p[i]; }
    }

    float4 a0[4], a1[4];
    #pragma unroll
    for (int i = 0; i < 4; ++i) {
        a0[i] = make_float4(0.f, 0.f, 0.f, 0.f);
        a1[i] = make_float4(0.f, 0.f, 0.f, 0.f);
    }
    float sum0 = 0.f, sum1 = 0.f;
    const float* kbase = qsF + 128 + head * 16;
    const float* vbase = qsF + 256 + head * 16;

    #pragma unroll 2
    for (int m = 0; m < 64; ++m) {
        const float4* kp = (const float4*)(kbase + (size_t)m * QS_STRIDE);
        float4 k0 = kp[0], k1 = kp[1], k2 = kp[2], k3 = kp[3];
        float s0 = dot4(q0[0], k0) + dot4(q0[1], k1) + dot4(q0[2], k2) + dot4(q0[3], k3);
        float s1 = dot4(q1[0], k0) + dot4(q1[1], k1) + dot4(q1[2], k2) + dot4(q1[3], k3);

        unsigned pmm = (unsigned)(pm >> m) & 1u;
        float e0 = (pmm == p0) ? __expf(s0 * 0.25f) : 0.f;
        float e1 = (pmm == p1) ? __expf(s1 * 0.25f) : 0.f;
        sum0 += e0;
        sum1 += e1;

        const float4* vp = (const float4*)(vbase + (size_t)m * QS_STRIDE);
        float4 v0 = vp[0], v1 = vp[1], v2 = vp[2], v3 = vp[3];
        a0[0].x = fmaf(e0, v0.x, a0[0].x); a0[0].y = fmaf(e0, v0.y, a0[0].y);
        a0[0].z = fmaf(e0, v0.z, a0[0].z); a0[0].w = fmaf(e0, v0.w, a0[0].w);
        a0[1].x = fmaf(e0, v1.x, a0[1].x); a0[1].y = fmaf(e0, v1.y, a0[1].y);
        a0[1].z = fmaf(e0, v1.z, a0[1].z); a0[1].w = fmaf(e0, v1.w, a0[1].w);
        a0[2].x = fmaf(e0, v2.x, a0[2].x); a0[2].y = fmaf(e0, v2.y, a0[2].y);
        a0[2].z = fmaf(e0, v2.z, a0[2].z); a0[2].w = fmaf(e0, v2.w, a0[2].w);
        a0[3].x = fmaf(e0, v3.x, a0[3].x); a0[3].y = fmaf(e0, v3.y, a0[3].y);
        a0[3].z = fmaf(e0, v3.z, a0[3].z); a0[3].w = fmaf(e0, v3.w, a0[3].w);
        a1[0].x = fmaf(e1, v0.x, a1[0].x); a1[0].y = fmaf(e1, v0.y, a1[0].y);
        a1[0].z = fmaf(e1, v0.z, a1[0].z); a1[0].w = fmaf(e1, v0.w, a1[0].w);
        a1[1].x = fmaf(e1, v1.x, a1[1].x); a1[1].y = fmaf(e1, v1.y, a1[1].y);
        a1[1].z = fmaf(e1, v1.z, a1[1].z); a1[1].w = fmaf(e1, v1.w, a1[1].w);
        a1[2].x = fmaf(e1, v2.x, a1[2].x); a1[2].y = fmaf(e1, v2.y, a1[2].y);
        a1[2].z = fmaf(e1, v2.z, a1[2].z); a1[2].w = fmaf(e1, v2.w, a1[2].w);
        a1[3].x = fmaf(e1, v3.x, a1[3].x); a1[3].y = fmaf(e1, v3.y, a1[3].y);
        a1[3].z = fmaf(e1, v3.z, a1[3].z); a1[3].w = fmaf(e1, v3.w, a1[3].w);
    }
    const float inv0 = 1.0f / sum0;
    const float inv1 = 1.0f / sum1;

    // ---- store Y (hi/lo) into A bufs (A region already free) ----
    #pragma unroll
    for (int j = 0; j < 4; ++j) {
        int c = head * 16 + 4 * j;
        split_pair(smemc + SM_AHI, smemc + SM_ALO, r0, c,     AST, a0[j].x * inv0, a0[j].y * inv0);
        split_pair(smemc + SM_AHI, smemc + SM_ALO, r0, c + 2, AST, a0[j].z * inv0, a0[j].w * inv0);
        split_pair(smemc + SM_AHI, smemc + SM_ALO, r1, c,     AST, a1[j].x * inv1, a1[j].y * inv1);
        split_pair(smemc + SM_AHI, smemc + SM_ALO, r1, c + 2, AST, a1[j].z * inv1, a1[j].w * inv1);
    }
    CP_WAIT0();
    __syncthreads();   // Y tiles + conv B ready

    // ---------------- phase 4: conv GEMM (64 vox x 128 out ch) ---------------
    float cacc[2][4][4];
    #pragma unroll
    for (int mt = 0; mt < 2; ++mt)
        #pragma unroll
        for (int nt = 0; nt < 4; ++nt)
            #pragma unroll
            for (int e = 0; e < 4; ++e) cacc[mt][nt][e] = 0.f;

    mma_block(aHi, aLo, bHi, bLo, lane, wm, wn, cacc);

    #pragma unroll
    for (int mt = 0; mt < 2; ++mt) {
        int m0 = wm * 32 + mt * 16 + (lane >> 2);
        int m1 = m0 + 8;
        int gz0 = z0 + (m0 >> 4), gy0 = y0 + ((m0 >> 2) & 3), gx0 = x0 + (m0 & 3);
        int gz1 = z0 + (m1 >> 4), gy1 = y0 + ((m1 >> 2) & 3), gx1 = x0 + (m1 & 3);
        bool ok0 = (gz0 < D0 && gy0 < H0 && gx0 < W0);
        bool ok1 = (gz1 < D0 && gy1 < H0 && gx1 < W0);
        size_t va0 = (size_t)(gz0 * H0 + gy0) * W0 + gx0;
        size_t va1 = (size_t)(gz1 * H0 + gy1) * W0 + gx1;
        #pragma unroll
        for (int nt = 0; nt < 4; ++nt) {
            int o = wn * 32 + nt * 8 + 2 * (lane & 3);
            float2 cb = *(const float2*)(conv_b + o);
            if (ok0) {
                out[(size_t)o * MTOT + va0]       = cacc[mt][nt][0] + cb.x;
                out[(size_t)(o + 1) * MTOT + va0] = cacc[mt][nt][1] + cb.y;
            }
            if (ok1) {
                out[(size_t)o * MTOT + va1]       = cacc[mt][nt][2] + cb.x;
                out[(size_t)(o + 1) * MTOT + va1] = cacc[mt][nt][3] + cb.y;
            }
        }
    }
}

extern "C" void kernel_launch(void* const* d_in, const int* in_sizes, int n_in,
                              void* d_out, int out_size)
{
    const float* x      = (const float*)d_in[0];
    const float* qkv_w  = (const float*)d_in[1];
    const float* qkv_b  = (const float*)d_in[2];
    const float* conv_w = (const float*)d_in[3];
    const float* conv_b = (const float*)d_in[4];
    float* out = (float*)d_out;

    prep_weights<<<64, 256>>>(qkv_w, conv_w);

    cudaFuncSetAttribute(fused_window_attn_mma,
                         cudaFuncAttributeMaxDynamicSharedMemorySize, SMEM_BYTES);

    fused_window_attn_mma<<<4096, 256, SMEM_BYTES>>>(x, qkv_b, conv_b, out);
}

// round 8
// speedup vs baseline: 1.3976x; 1.3976x over previous
#include <cuda_runtime.h>
#include <cuda_bf16.h>
#include <cstdint>

// Fused 3D windowed attention block — fully tensor-core (mma.sync bf16 3-split):
// QKV GEMM + attention (S=QK^T, PV) + 1x1 conv. 1 window/CTA, 512 threads (16 warps).
// Warp grid: wm = wid>>3 (row half 0..1), wn = wid&7 (16-col slice / head).

#define D0 30
#define H0 62
#define W0 126
#define MTOT (30*62*126)

#define AST 136     // halves/row, A & Y tiles (64 rows)
#define BST 136     // halves/row, B weight tiles (128 rows)
#define KST 136     // halves/row, K tiles (64 rows)
#define VTST 72     // halves/row, Vt tiles (128 dim rows x 64 keys + pad)

#define SM_AHI  0
#define SM_ALO  17408
#define SM_BHI  34816
#define SM_BLO  69632
#define SM_KHI  104448
#define SM_KLO  121856
#define SM_VTHI 139264
#define SM_VTLO 157696
#define SM_BIAS 176128
#define SMEM_BYTES 177664

// pre-split weights: [mat][n 128][k 128] halves. mats: 0=Q,1=K,2=V,3=conv
__device__ __align__(256) __nv_bfloat16 g_whi[4 * 128 * 128];
__device__ __align__(256) __nv_bfloat16 g_wlo[4 * 128 * 128];

__device__ __forceinline__ uint32_t smem_u32(const void* p) {
    uint32_t a;
    asm("{ .reg .u64 t; cvta.to.shared.u64 t, %1; cvt.u32.u64 %0, t; }"
        : "=r"(a) : "l"(p));
    return a;
}
__device__ __forceinline__ void ldsm4(uint32_t (&r)[4], uint32_t addr) {
    asm volatile("ldmatrix.sync.aligned.m8n8.x4.shared.b16 {%0,%1,%2,%3}, [%4];"
                 : "=r"(r[0]), "=r"(r[1]), "=r"(r[2]), "=r"(r[3]) : "r"(addr));
}
__device__ __forceinline__ void mma16816(float (&d)[4], const uint32_t (&a)[4],
                                         uint32_t b0, uint32_t b1) {
    asm volatile("mma.sync.aligned.m16n8k16.row.col.f32.bf16.bf16.f32 "
                 "{%0,%1,%2,%3}, {%4,%5,%6,%7}, {%8,%9}, {%0,%1,%2,%3};"
                 : "+f"(d[0]), "+f"(d[1]), "+f"(d[2]), "+f"(d[3])
                 : "r"(a[0]), "r"(a[1]), "r"(a[2]), "r"(a[3]), "r"(b0), "r"(b1));
}
__device__ __forceinline__ void cp_async16(uint32_t saddr, const void* gaddr) {
    asm volatile("cp.async.cg.shared.global [%0], [%1], 16;" :: "r"(saddr), "l"(gaddr));
}
#define CP_COMMIT() asm volatile("cp.async.commit_group;" ::: "memory")
#define CP_WAIT0()  asm volatile("cp.async.wait_group 0;" ::: "memory")

__device__ __forceinline__ uint32_t bf2_u32(__nv_bfloat16 a, __nv_bfloat16 b) {
    __nv_bfloat162 p = __halves2bfloat162(a, b);
    return *(uint32_t*)&p;
}
// pack (a,b) into bf16x2 hi frag; residual lo frag out-param
__device__ __forceinline__ uint32_t split_frag(float a, float b, uint32_t& lo) {
    __nv_bfloat16 h0 = __float2bfloat16(a), h1 = __float2bfloat16(b);
    __nv_bfloat16 l0 = __float2bfloat16(a - __bfloat162float(h0));
    __nv_bfloat16 l1 = __float2bfloat16(b - __bfloat162float(h1));
    lo = bf2_u32(l0, l1);
    return bf2_u32(h0, h1);
}
// store (v0,v1) hi/lo at (row, col..col+1)
__device__ __forceinline__ void split_pair(char* hiB, char* loB, int row, int col,
                                           int stride, float v0, float v1) {
    uint32_t lo, hi = split_frag(v0, v1, lo);
    int off = (row * stride + col) * 2;
    *(uint32_t*)(hiB + off) = hi;
    *(uint32_t*)(loB + off) = lo;
}
__device__ __forceinline__ void split1(char* hiB, char* loB, int off_h, float v) {
    __nv_bfloat16 h = __float2bfloat16(v);
    __nv_bfloat16 l = __float2bfloat16(v - __bfloat162float(h));
    *(__nv_bfloat16*)(hiB + 2 * off_h) = h;
    *(__nv_bfloat16*)(loB + 2 * off_h) = l;
}

// fill B hi/lo tiles from pre-split gmem via cp.async (512 threads)
__device__ __forceinline__ void fillB_async(int mat, uint32_t sb, int t) {
    const __nv_bfloat16* gh = g_whi + mat * 16384;
    const __nv_bfloat16* gl = g_wlo + mat * 16384;
    #pragma unroll
    for (int it = 0; it < 4; ++it) {
        int id = t + 512 * it;      // 0..2047
        int n = id >> 4, c = id & 15;
        uint32_t so = (uint32_t)((n * BST + c * 8) * 2);
        const int go = n * 128 + c * 8;
        cp_async16(sb + SM_BHI + so, gh + go);
        cp_async16(sb + SM_BLO + so, gl + go);
    }
}

// 32x16x128 warp GEMM, 3-split bf16: acc[2 mt][2 nt][4]
__device__ __forceinline__ void gemm_tile(uint32_t aHi, uint32_t aLo,
                                          uint32_t bHi, uint32_t bLo,
                                          int lane, int wm, int wn,
                                          float acc[2][2][4]) {
    const int r8 = lane & 7, g = lane >> 3;
    const uint32_t aoff = (uint32_t)(((wm * 32 + r8 + 8 * (g & 1)) * AST + 8 * (g >> 1)) * 2);
    const uint32_t boff = (uint32_t)(((wn * 16 + r8 + 8 * ((lane >> 4) & 1)) * BST
                                      + 8 * ((lane >> 3) & 1)) * 2);
    #pragma unroll
    for (int kk = 0; kk < 8; ++kk) {
        uint32_t ah[2][4], al[2][4], bh[4], bl[4];
        #pragma unroll
        for (int mt = 0; mt < 2; ++mt) {
            uint32_t o = aoff + (uint32_t)((mt * 16 * AST + kk * 16) * 2);
            ldsm4(ah[mt], aHi + o);
            ldsm4(al[mt], aLo + o);
        }
        {
            uint32_t o = boff + (uint32_t)((kk * 16) * 2);
            ldsm4(bh, bHi + o);
            ldsm4(bl, bLo + o);
        }
        #pragma unroll
        for (int mt = 0; mt < 2; ++mt)
            #pragma unroll
            for (int s = 0; s < 2; ++s) {
                mma16816(acc[mt][s], ah[mt], bh[2 * s], bh[2 * s + 1]);
                mma16816(acc[mt][s], ah[mt], bl[2 * s], bl[2 * s + 1]);
                mma16816(acc[mt][s], al[mt], bh[2 * s], bh[2 * s + 1]);
            }
    }
}

// ---------------- prep kernel: split weights into g_whi/g_wlo ----------------
__global__ void prep_weights(const float* __restrict__ qkv_w,
                             const float* __restrict__ conv_w)
{
    int t = blockIdx.x * 256 + threadIdx.x;   // 0..16383
    int base = t * 4;
    const float* src = (base < 49152) ? (qkv_w + base) : (conv_w + (base - 49152));
    float4 v = *(const float4*)src;
    __nv_bfloat16 h0 = __float2bfloat16(v.x), h1 = __float2bfloat16(v.y);
    __nv_bfloat16 h2 = __float2bfloat16(v.z), h3 = __float2bfloat16(v.w);
    __nv_bfloat16 l0 = __float2bfloat16(v.x - __bfloat162float(h0));
    __nv_bfloat16 l1 = __float2bfloat16(v.y - __bfloat162float(h1));
    __nv_bfloat16 l2 = __float2bfloat16(v.z - __bfloat162float(h2));
    __nv_bfloat16 l3 = __float2bfloat16(v.w - __bfloat162float(h3));
    *(__nv_bfloat162*)(g_whi + base)     = __halves2bfloat162(h0, h1);
    *(__nv_bfloat162*)(g_whi + base + 2) = __halves2bfloat162(h2, h3);
    *(__nv_bfloat162*)(g_wlo + base)     = __halves2bfloat162(l0, l1);
    *(__nv_bfloat162*)(g_wlo + base + 2) = __halves2bfloat162(l2, l3);
}

// ---------------- main kernel ----------------
__global__ void __launch_bounds__(512, 1)
fused_window_attn_mma(const float* __restrict__ x,
                      const float* __restrict__ qkv_b,
                      const float* __restrict__ conv_b,
                      float* __restrict__ out)
{
    extern __shared__ char smemc[];
    const uint32_t sb = smem_u32(smemc);
    float* biasS = (float*)(smemc + SM_BIAS);

    const int t    = threadIdx.x;
    const int wid  = t >> 5;
    const int lane = t & 31;
    const int wm = wid >> 3;     // row half (0..1)
    const int wn = wid & 7;      // col slice / head (0..7)
    const int wi = blockIdx.x;
    const int bz = wi >> 9, by = (wi >> 5) & 15, bx = wi & 31;
    const int z0 = bz * 4, y0 = by * 4, x0 = bx * 4;

    // ---- phase 1: fill B(K weights), gather x -> A hi/lo, bias ----
    fillB_async(1, sb, t);
    CP_COMMIT();
    #pragma unroll
    for (int it = 0; it < 8; ++it) {
        int idx = t + 512 * it;      // 0..4095
        int l  = idx & 63;
        int cp = idx >> 6;
        int gz = z0 + (l >> 4);
        int gy = y0 + ((l >> 2) & 3);
        int gx = x0 + (l & 3);
        float v0 = 0.f, v1 = 0.f;
        if (gz < D0 && gy < H0 && gx < W0) {
            size_t base = (size_t)(gz * H0 + gy) * W0 + gx;
            v0 = x[(size_t)(2 * cp) * MTOT + base];
            v1 = x[(size_t)(2 * cp + 1) * MTOT + base];
        }
        split_pair(smemc + SM_AHI, smemc + SM_ALO, l, 2 * cp, AST, v0, v1);
    }
    if (t < 384) biasS[t] = qkv_b[t];
    CP_WAIT0();
    __syncthreads();

    const uint32_t aHi = sb + SM_AHI, aLo = sb + SM_ALO;
    const uint32_t bHi = sb + SM_BHI, bLo = sb + SM_BLO;

    const int erow = wm * 32 + (lane >> 2);     // epilogue row base (+mt*16, +8)
    const int ecol = wn * 16 + 2 * (lane & 3);  // epilogue col base (+nt*8, +1)

    // ---- K chunk ----
    {
        float acc[2][2][4] = {};
        gemm_tile(aHi, aLo, bHi, bLo, lane, wm, wn, acc);
        __syncthreads();
        fillB_async(2, sb, t);       // V weights
        CP_COMMIT();
        #pragma unroll
        for (int mt = 0; mt < 2; ++mt)
            #pragma unroll
            for (int nt = 0; nt < 2; ++nt) {
                int col = ecol + nt * 8;
                float2 bv = *(const float2*)(biasS + 128 + col);
                int r0 = erow + mt * 16;
                split_pair(smemc + SM_KHI, smemc + SM_KLO, r0, col, KST,
                           acc[mt][nt][0] + bv.x, acc[mt][nt][1] + bv.y);
                split_pair(smemc + SM_KHI, smemc + SM_KLO, r0 + 8, col, KST,
                           acc[mt][nt][2] + bv.x, acc[mt][nt][3] + bv.y);
            }
        CP_WAIT0();
        __syncthreads();
    }

    // ---- V chunk (store transposed: Vt[dim][key]) ----
    {
        float acc[2][2][4] = {};
        gemm_tile(aHi, aLo, bHi, bLo, lane, wm, wn, acc);
        __syncthreads();
        fillB_async(0, sb, t);       // Q weights
        CP_COMMIT();
        #pragma unroll
        for (int mt = 0; mt < 2; ++mt)
            #pragma unroll
            for (int nt = 0; nt < 2; ++nt) {
                int col = ecol + nt * 8;
                float2 bv = *(const float2*)(biasS + 256 + col);
                int r0 = erow + mt * 16;
                split1(smemc + SM_VTHI, smemc + SM_VTLO, col * VTST + r0,           acc[mt][nt][0] + bv.x);
                split1(smemc + SM_VTHI, smemc + SM_VTLO, (col + 1) * VTST + r0,     acc[mt][nt][1] + bv.y);
                split1(smemc + SM_VTHI, smemc + SM_VTLO, col * VTST + r0 + 8,       acc[mt][nt][2] + bv.x);
                split1(smemc + SM_VTHI, smemc + SM_VTLO, (col + 1) * VTST + r0 + 8, acc[mt][nt][3] + bv.y);
            }
        CP_WAIT0();
        __syncthreads();
    }

    // ---- Q chunk (stays in registers as mma A-fragments) ----
    uint32_t qh[2][4], ql[2][4];
    {
        float acc[2][2][4] = {};
        gemm_tile(aHi, aLo, bHi, bLo, lane, wm, wn, acc);
        __syncthreads();             // all warps done reading A & B
        fillB_async(3, sb, t);       // conv weights — overlaps attention
        CP_COMMIT();
        #pragma unroll
        for (int mt = 0; mt < 2; ++mt) {
            #pragma unroll
            for (int nt = 0; nt < 2; ++nt) {
                int col = ecol + nt * 8;
                float2 bv = *(const float2*)(biasS + col);
                float d0 = acc[mt][nt][0] + bv.x, d1 = acc[mt][nt][1] + bv.y;
                float d2 = acc[mt][nt][2] + bv.x, d3 = acc[mt][nt][3] + bv.y;
                qh[mt][2 * nt]     = split_frag(d0, d1, ql[mt][2 * nt]);
                qh[mt][2 * nt + 1] = split_frag(d2, d3, ql[mt][2 * nt + 1]);
            }
        }
    }

    // ---- attention (tensor cores), warp = (rowhalf wm, head wn) ----
    unsigned long long pm = 0ull;
    if (bz == 7 || by == 15 || bx == 31) {
        #pragma unroll
        for (int m = 0; m < 64; ++m) {
            bool p = (bz == 7 && (m >> 4) >= 2) ||
                     (by == 15 && ((m >> 2) & 3) >= 2) ||
                     (bx == 31 && (m & 3) >= 2);
            pm |= (unsigned long long)(p ? 1u : 0u) << m;
        }
    }
    const int head = wn;
    unsigned rp[2][2];
    #pragma unroll
    for (int mt = 0; mt < 2; ++mt) {
        int r0 = wm * 32 + mt * 16 + (lane >> 2);
        rp[mt][0] = (unsigned)(pm >> r0) & 1u;
        rp[mt][1] = (unsigned)(pm >> (r0 + 8)) & 1u;
    }

    const int r8 = lane & 7;
    const uint32_t koff = (uint32_t)(((r8 + 8 * ((lane >> 4) & 1)) * KST
                                      + head * 16 + 8 * ((lane >> 3) & 1)) * 2);
    const uint32_t voff = (uint32_t)(((head * 16 + r8 + 8 * ((lane >> 4) & 1)) * VTST
                                      + 8 * ((lane >> 3) & 1)) * 2);

    float oacc[2][2][4] = {};
    float rsum[2][2] = {};

    #pragma unroll
    for (int g4 = 0; g4 < 4; ++g4) {
        uint32_t kh[4], kl[4];
        ldsm4(kh, sb + SM_KHI + koff + (uint32_t)(g4 * 16 * KST * 2));
        ldsm4(kl, sb + SM_KLO + koff + (uint32_t)(g4 * 16 * KST * 2));

        float sacc[2][2][4] = {};
        #pragma unroll
        for (int mt = 0; mt < 2; ++mt)
            #pragma unroll
            for (int s = 0; s < 2; ++s) {
                mma16816(sacc[mt][s], qh[mt], kh[2 * s], kh[2 * s + 1]);
                mma16816(sacc[mt][s], qh[mt], kl[2 * s], kl[2 * s + 1]);
                mma16816(sacc[mt][s], ql[mt], kh[2 * s], kh[2 * s + 1]);
            }

        uint32_t ph[2][4], pl[2][4];
        #pragma unroll
        for (int s = 0; s < 2; ++s) {
            int k0 = g4 * 16 + s * 8 + 2 * (lane & 3);
            unsigned cp0 = (unsigned)(pm >> k0) & 1u;
            unsigned cp1 = (unsigned)(pm >> (k0 + 1)) & 1u;
            #pragma unroll
            for (int mt = 0; mt < 2; ++mt) {
                float e0 = (cp0 == rp[mt][0]) ? __expf(0.25f * sacc[mt][s][0]) : 0.f;
                float e1 = (cp1 == rp[mt][0]) ? __expf(0.25f * sacc[mt][s][1]) : 0.f;
                float e2 = (cp0 == rp[mt][1]) ? __expf(0.25f * sacc[mt][s][2]) : 0.f;
                float e3 = (cp1 == rp[mt][1]) ? __expf(0.25f * sacc[mt][s][3]) : 0.f;
                rsum[mt][0] += e0 + e1;
                rsum[mt][1] += e2 + e3;
                ph[mt][2 * s]     = split_frag(e0, e1, pl[mt][2 * s]);
                ph[mt][2 * s + 1] = split_frag(e2, e3, pl[mt][2 * s + 1]);
            }
        }

        uint32_t vh[4], vl[4];
        ldsm4(vh, sb + SM_VTHI + voff + (uint32_t)(g4 * 16 * 2));
        ldsm4(vl, sb + SM_VTLO + voff + (uint32_t)(g4 * 16 * 2));
        #pragma unroll
        for (int mt = 0; mt < 2; ++mt)
            #pragma unroll
            for (int sp = 0; sp < 2; ++sp) {
                mma16816(oacc[mt][sp], ph[mt], vh[2 * sp], vh[2 * sp + 1]);
                mma16816(oacc[mt][sp], ph[mt], vl[2 * sp], vl[2 * sp + 1]);
                mma16816(oacc[mt][sp], pl[mt], vh[2 * sp], vh[2 * sp + 1]);
            }
    }

    // row sums across the 4-lane quad, then normalize and store Y into A region
    #pragma unroll
    for (int mt = 0; mt < 2; ++mt)
        #pragma unroll
        for (int h = 0; h < 2; ++h) {
            rsum[mt][h] += __shfl_xor_sync(0xFFFFFFFFu, rsum[mt][h], 1);
            rsum[mt][h] += __shfl_xor_sync(0xFFFFFFFFu, rsum[mt][h], 2);
            rsum[mt][h] = 1.0f / rsum[mt][h];
        }
    #pragma unroll
    for (int mt = 0; mt < 2; ++mt)
        #pragma unroll
        for (int sp = 0; sp < 2; ++sp) {
            int col = head * 16 + sp * 8 + 2 * (lane & 3);
            int r0 = wm * 32 + mt * 16 + (lane >> 2);
            split_pair(smemc + SM_AHI, smemc + SM_ALO, r0, col, AST,
                       oacc[mt][sp][0] * rsum[mt][0], oacc[mt][sp][1] * rsum[mt][0]);
            split_pair(smemc + SM_AHI, smemc + SM_ALO, r0 + 8, col, AST,
                       oacc[mt][sp][2] * rsum[mt][1], oacc[mt][sp][3] * rsum[mt][1]);
        }
    CP_WAIT0();
    __syncthreads();   // Y tiles + conv B ready

    // ---- conv GEMM + scattered output ----
    {
        float acc[2][2][4] = {};
        gemm_tile(aHi, aLo, bHi, bLo, lane, wm, wn, acc);
        #pragma unroll
        for (int mt = 0; mt < 2; ++mt) {
            int m0 = erow + mt * 16;
            int m1 = m0 + 8;
            int gz0 = z0 + (m0 >> 4), gy0 = y0 + ((m0 >> 2) & 3), gx0 = x0 + (m0 & 3);
            int gz1 = z0 + (m1 >> 4), gy1 = y0 + ((m1 >> 2) & 3), gx1 = x0 + (m1 & 3);
            bool ok0 = (gz0 < D0 && gy0 < H0 && gx0 < W0);
            bool ok1 = (gz1 < D0 && gy1 < H0 && gx1 < W0);
            size_t va0 = (size_t)(gz0 * H0 + gy0) * W0 + gx0;
            size_t va1 = (size_t)(gz1 * H0 + gy1) * W0 + gx1;
            #pragma unroll
            for (int nt = 0; nt < 2; ++nt) {
                int o = ecol + nt * 8;
                float2 cb = *(const float2*)(conv_b + o);
                if (ok0) {
                    out[(size_t)o * MTOT + va0]       = acc[mt][nt][0] + cb.x;
                    out[(size_t)(o + 1) * MTOT + va0] = acc[mt][nt][1] + cb.y;
                }
                if (ok1) {
                    out[(size_t)o * MTOT + va1]       = acc[mt][nt][2] + cb.x;
                    out[(size_t)(o + 1) * MTOT + va1] = acc[mt][nt][3] + cb.y;
                }
            }
        }
    }
}

extern "C" void kernel_launch(void* const* d_in, const int* in_sizes, int n_in,
                              void* d_out, int out_size)
{
    const float* x      = (const float*)d_in[0];
    const float* qkv_w  = (const float*)d_in[1];
    const float* qkv_b  = (const float*)d_in[2];
    const float* conv_w = (const float*)d_in[3];
    const float* conv_b = (const float*)d_in[4];
    float* out = (float*)d_out;

    prep_weights<<<64, 256>>>(qkv_w, conv_w);

    cudaFuncSetAttribute(fused_window_attn_mma,
                         cudaFuncAttributeMaxDynamicSharedMemorySize, SMEM_BYTES);

    fused_window_attn_mma<<<4096, 512, SMEM_BYTES>>>(x, qkv_b, conv_b, out);
}

// round 9
// speedup vs baseline: 1.6065x; 1.1495x over previous
#include <cuda_runtime.h>
#include <cuda_bf16.h>
#include <cstdint>

// Fused 3D windowed attention block — fully tensor-core, bf16 3-split.
// R9: B-weights pre-laid-out in mma fragment order in gmem (no B SMEM, no fill syncs),
//     SMEM 108KB -> 2 CTAs/SM. 1 window/CTA, 512 threads (16 warps).

#define D0 30
#define H0 62
#define W0 126
#define MTOT (30*62*126)

#define AST 136     // halves/row, A & Y tiles (64 rows)
#define KST 136     // halves/row, K tiles (64 rows)
#define VTST 72     // halves/row, Vt tiles (128 dim rows x 64 keys + pad)

#define SM_AHI  0
#define SM_ALO  17408
#define SM_KHI  34816
#define SM_KLO  52224
#define SM_VTHI 69632
#define SM_VTLO 88064
#define SM_BIAS 106496
#define SMEM_BYTES 108032

// weights in B-fragment order: [mat 0..3][wn 0..7][kk 0..7][lane 0..31] x uint4
// mats: 0=Q, 1=K, 2=V, 3=conv
__device__ __align__(256) uint4 g_bh4[4 * 8 * 8 * 32];
__device__ __align__(256) uint4 g_bl4[4 * 8 * 8 * 32];

__device__ __forceinline__ uint32_t smem_u32(const void* p) {
    uint32_t a;
    asm("{ .reg .u64 t; cvta.to.shared.u64 t, %1; cvt.u32.u64 %0, t; }"
        : "=r"(a) : "l"(p));
    return a;
}
__device__ __forceinline__ void ldsm4(uint32_t (&r)[4], uint32_t addr) {
    asm volatile("ldmatrix.sync.aligned.m8n8.x4.shared.b16 {%0,%1,%2,%3}, [%4];"
                 : "=r"(r[0]), "=r"(r[1]), "=r"(r[2]), "=r"(r[3]) : "r"(addr));
}
__device__ __forceinline__ void mma16816(float (&d)[4], const uint32_t (&a)[4],
                                         uint32_t b0, uint32_t b1) {
    asm volatile("mma.sync.aligned.m16n8k16.row.col.f32.bf16.bf16.f32 "
                 "{%0,%1,%2,%3}, {%4,%5,%6,%7}, {%8,%9}, {%0,%1,%2,%3};"
                 : "+f"(d[0]), "+f"(d[1]), "+f"(d[2]), "+f"(d[3])
                 : "r"(a[0]), "r"(a[1]), "r"(a[2]), "r"(a[3]), "r"(b0), "r"(b1));
}
__device__ __forceinline__ uint32_t bf2_u32(__nv_bfloat16 a, __nv_bfloat16 b) {
    __nv_bfloat162 p = __halves2bfloat162(a, b);
    return *(uint32_t*)&p;
}
__device__ __forceinline__ uint32_t split_frag(float a, float b, uint32_t& lo) {
    __nv_bfloat16 h0 = __float2bfloat16(a), h1 = __float2bfloat16(b);
    __nv_bfloat16 l0 = __float2bfloat16(a - __bfloat162float(h0));
    __nv_bfloat16 l1 = __float2bfloat16(b - __bfloat162float(h1));
    lo = bf2_u32(l0, l1);
    return bf2_u32(h0, h1);
}
__device__ __forceinline__ void split_pair(char* hiB, char* loB, int row, int col,
                                           int stride, float v0, float v1) {
    uint32_t lo, hi = split_frag(v0, v1, lo);
    int off = (row * stride + col) * 2;
    *(uint32_t*)(hiB + off) = hi;
    *(uint32_t*)(loB + off) = lo;
}
__device__ __forceinline__ void split1(char* hiB, char* loB, int off_h, float v) {
    __nv_bfloat16 h = __float2bfloat16(v);
    __nv_bfloat16 l = __float2bfloat16(v - __bfloat162float(h));
    *(__nv_bfloat16*)(hiB + 2 * off_h) = h;
    *(__nv_bfloat16*)(loB + 2 * off_h) = l;
}

// 32x16x128 warp GEMM, 3-split bf16, B fragments streamed from gmem
__device__ __forceinline__ void gemm_tile_g(uint32_t aHi, uint32_t aLo,
                                            const uint4* __restrict__ bh,
                                            const uint4* __restrict__ bl,
                                            int lane, int wm,
                                            float acc[2][2][4]) {
    const int r8 = lane & 7, g = lane >> 3;
    const uint32_t aoff = (uint32_t)(((wm * 32 + r8 + 8 * (g & 1)) * AST + 8 * (g >> 1)) * 2);
    #pragma unroll
    for (int kk = 0; kk < 8; ++kk) {
        uint4 BH = __ldg(bh + kk * 32);
        uint4 BL = __ldg(bl + kk * 32);
        uint32_t ah[2][4], al[2][4];
        #pragma unroll
        for (int mt = 0; mt < 2; ++mt) {
            uint32_t o = aoff + (uint32_t)((mt * 16 * AST + kk * 16) * 2);
            ldsm4(ah[mt], aHi + o);
            ldsm4(al[mt], aLo + o);
        }
        #pragma unroll
        for (int mt = 0; mt < 2; ++mt) {
            mma16816(acc[mt][0], ah[mt], BH.x, BH.y);
            mma16816(acc[mt][0], ah[mt], BL.x, BL.y);
            mma16816(acc[mt][0], al[mt], BH.x, BH.y);
            mma16816(acc[mt][1], ah[mt], BH.z, BH.w);
            mma16816(acc[mt][1], ah[mt], BL.z, BL.w);
            mma16816(acc[mt][1], al[mt], BH.z, BH.w);
        }
    }
}

// ---------------- prep: weights -> hi/lo B-fragment layout ----------------
__global__ void prep_weights(const float* __restrict__ qkv_w,
                             const float* __restrict__ conv_w)
{
    int tid = blockIdx.x * 256 + threadIdx.x;    // 0..8191
    int lane = tid & 31;
    int kk   = (tid >> 5) & 7;
    int wn   = (tid >> 8) & 7;
    int mat  = tid >> 11;
    const float* W = (mat < 3) ? (qkv_w + mat * 16384) : conv_w;

    uint32_t hi[4], lo[4];
    #pragma unroll
    for (int r = 0; r < 4; ++r) {
        int n = wn * 16 + (r >> 1) * 8 + (lane >> 2);
        int k = kk * 16 + (r & 1) * 8 + 2 * (lane & 3);
        float v0 = W[n * 128 + k];
        float v1 = W[n * 128 + k + 1];
        hi[r] = split_frag(v0, v1, lo[r]);
    }
    g_bh4[tid] = make_uint4(hi[0], hi[1], hi[2], hi[3]);
    g_bl4[tid] = make_uint4(lo[0], lo[1], lo[2], lo[3]);
}

// ---------------- main kernel ----------------
__global__ void __launch_bounds__(512, 2)
fused_window_attn_mma(const float* __restrict__ x,
                      const float* __restrict__ qkv_b,
                      const float* __restrict__ conv_b,
                      float* __restrict__ out)
{
    extern __shared__ char smemc[];
    const uint32_t sb = smem_u32(smemc);
    float* biasS = (float*)(smemc + SM_BIAS);

    const int t    = threadIdx.x;
    const int wid  = t >> 5;
    const int lane = t & 31;
    const int wm = wid >> 3;     // row half (0..1)
    const int wn = wid & 7;      // col slice / head (0..7)
    const int wi = blockIdx.x;
    const int bz = wi >> 9, by = (wi >> 5) & 15, bx = wi & 31;
    const int z0 = bz * 4, y0 = by * 4, x0 = bx * 4;

    // ---- phase 1: gather x -> A hi/lo, bias ----
    #pragma unroll
    for (int it = 0; it < 8; ++it) {
        int idx = t + 512 * it;      // 0..4095
        int l  = idx & 63;
        int cp = idx >> 6;
        int gz = z0 + (l >> 4);
        int gy = y0 + ((l >> 2) & 3);
        int gx = x0 + (l & 3);
        float v0 = 0.f, v1 = 0.f;
        if (gz < D0 && gy < H0 && gx < W0) {
            size_t base = (size_t)(gz * H0 + gy) * W0 + gx;
            v0 = x[(size_t)(2 * cp) * MTOT + base];
            v1 = x[(size_t)(2 * cp + 1) * MTOT + base];
        }
        split_pair(smemc + SM_AHI, smemc + SM_ALO, l, 2 * cp, AST, v0, v1);
    }
    if (t < 384) biasS[t] = qkv_b[t];
    __syncthreads();

    const uint32_t aHi = sb + SM_AHI, aLo = sb + SM_ALO;
    const int fragbase = wn * 8 * 32 + lane;      // within one mat
    const uint4* bhQ = g_bh4 + 0 * 2048 + fragbase;
    const uint4* blQ = g_bl4 + 0 * 2048 + fragbase;
    const uint4* bhK = g_bh4 + 1 * 2048 + fragbase;
    const uint4* blK = g_bl4 + 1 * 2048 + fragbase;
    const uint4* bhV = g_bh4 + 2 * 2048 + fragbase;
    const uint4* blV = g_bl4 + 2 * 2048 + fragbase;
    const uint4* bhC = g_bh4 + 3 * 2048 + fragbase;
    const uint4* blC = g_bl4 + 3 * 2048 + fragbase;

    const int erow = wm * 32 + (lane >> 2);
    const int ecol = wn * 16 + 2 * (lane & 3);

    // ---- K chunk -> K smem ----
    {
        float acc[2][2][4] = {};
        gemm_tile_g(aHi, aLo, bhK, blK, lane, wm, acc);
        #pragma unroll
        for (int mt = 0; mt < 2; ++mt)
            #pragma unroll
            for (int nt = 0; nt < 2; ++nt) {
                int col = ecol + nt * 8;
                float2 bv = *(const float2*)(biasS + 128 + col);
                int r0 = erow + mt * 16;
                split_pair(smemc + SM_KHI, smemc + SM_KLO, r0, col, KST,
                           acc[mt][nt][0] + bv.x, acc[mt][nt][1] + bv.y);
                split_pair(smemc + SM_KHI, smemc + SM_KLO, r0 + 8, col, KST,
                           acc[mt][nt][2] + bv.x, acc[mt][nt][3] + bv.y);
            }
    }

    // ---- V chunk -> Vt smem (transposed) ----
    {
        float acc[2][2][4] = {};
        gemm_tile_g(aHi, aLo, bhV, blV, lane, wm, acc);
        #pragma unroll
        for (int mt = 0; mt < 2; ++mt)
            #pragma unroll
            for (int nt = 0; nt < 2; ++nt) {
                int col = ecol + nt * 8;
                float2 bv = *(const float2*)(biasS + 256 + col);
                int r0 = erow + mt * 16;
                split1(smemc + SM_VTHI, smemc + SM_VTLO, col * VTST + r0,           acc[mt][nt][0] + bv.x);
                split1(smemc + SM_VTHI, smemc + SM_VTLO, (col + 1) * VTST + r0,     acc[mt][nt][1] + bv.y);
                split1(smemc + SM_VTHI, smemc + SM_VTLO, col * VTST + r0 + 8,       acc[mt][nt][2] + bv.x);
                split1(smemc + SM_VTHI, smemc + SM_VTLO, (col + 1) * VTST + r0 + 8, acc[mt][nt][3] + bv.y);
            }
    }

    // ---- Q chunk (stays in registers as mma A-fragments) ----
    uint32_t qh[2][4], ql[2][4];
    {
        float acc[2][2][4] = {};
        gemm_tile_g(aHi, aLo, bhQ, blQ, lane, wm, acc);
        #pragma unroll
        for (int mt = 0; mt < 2; ++mt) {
            #pragma unroll
            for (int nt = 0; nt < 2; ++nt) {
                int col = ecol + nt * 8;
                float2 bv = *(const float2*)(biasS + col);
                float d0 = acc[mt][nt][0] + bv.x, d1 = acc[mt][nt][1] + bv.y;
                float d2 = acc[mt][nt][2] + bv.x, d3 = acc[mt][nt][3] + bv.y;
                qh[mt][2 * nt]     = split_frag(d0, d1, ql[mt][2 * nt]);
                qh[mt][2 * nt + 1] = split_frag(d2, d3, ql[mt][2 * nt + 1]);
            }
        }
    }
    __syncthreads();   // K/Vt visible; all A reads done (Y store comes later)

    // ---- attention (tensor cores), warp = (rowhalf wm, head wn) ----
    unsigned long long pm = 0ull;
    if (bz == 7 || by == 15 || bx == 31) {
        #pragma unroll
        for (int m = 0; m < 64; ++m) {
            bool p = (bz == 7 && (m >> 4) >= 2) ||
                     (by == 15 && ((m >> 2) & 3) >= 2) ||
                     (bx == 31 && (m & 3) >= 2);
            pm |= (unsigned long long)(p ? 1u : 0u) << m;
        }
    }
    const int head = wn;
    unsigned rp[2][2];
    #pragma unroll
    for (int mt = 0; mt < 2; ++mt) {
        int r0 = wm * 32 + mt * 16 + (lane >> 2);
        rp[mt][0] = (unsigned)(pm >> r0) & 1u;
        rp[mt][1] = (unsigned)(pm >> (r0 + 8)) & 1u;
    }

    const int r8 = lane & 7;
    const uint32_t koff = (uint32_t)(((r8 + 8 * ((lane >> 4) & 1)) * KST
                                      + head * 16 + 8 * ((lane >> 3) & 1)) * 2);
    const uint32_t voff = (uint32_t)(((head * 16 + r8 + 8 * ((lane >> 4) & 1)) * VTST
                                      + 8 * ((lane >> 3) & 1)) * 2);

    float oacc[2][2][4] = {};
    float rsum[2][2] = {};

    #pragma unroll
    for (int g4 = 0; g4 < 4; ++g4) {
        uint32_t kh[4], kl[4];
        ldsm4(kh, sb + SM_KHI + koff + (uint32_t)(g4 * 16 * KST * 2));
        ldsm4(kl, sb + SM_KLO + koff + (uint32_t)(g4 * 16 * KST * 2));

        float sacc[2][2][4] = {};
        #pragma unroll
        for (int mt = 0; mt < 2; ++mt)
            #pragma unroll
            for (int s = 0; s < 2; ++s) {
                mma16816(sacc[mt][s], qh[mt], kh[2 * s], kh[2 * s + 1]);
                mma16816(sacc[mt][s], qh[mt], kl[2 * s], kl[2 * s + 1]);
                mma16816(sacc[mt][s], ql[mt], kh[2 * s], kh[2 * s + 1]);
            }

        uint32_t ph[2][4], pl[2][4];
        #pragma unroll
        for (int s = 0; s < 2; ++s) {
            int k0 = g4 * 16 + s * 8 + 2 * (lane & 3);
            unsigned cp0 = (unsigned)(pm >> k0) & 1u;
            unsigned cp1 = (unsigned)(pm >> (k0 + 1)) & 1u;
            #pragma unroll
            for (int mt = 0; mt < 2; ++mt) {
                float e0 = (cp0 == rp[mt][0]) ? __expf(0.25f * sacc[mt][s][0]) : 0.f;
                float e1 = (cp1 == rp[mt][0]) ? __expf(0.25f * sacc[mt][s][1]) : 0.f;
                float e2 = (cp0 == rp[mt][1]) ? __expf(0.25f * sacc[mt][s][2]) : 0.f;
                float e3 = (cp1 == rp[mt][1]) ? __expf(0.25f * sacc[mt][s][3]) : 0.f;
                rsum[mt][0] += e0 + e1;
                rsum[mt][1] += e2 + e3;
                ph[mt][2 * s]     = split_frag(e0, e1, pl[mt][2 * s]);
                ph[mt][2 * s + 1] = split_frag(e2, e3, pl[mt][2 * s + 1]);
            }
        }

        uint32_t vh[4], vl[4];
        ldsm4(vh, sb + SM_VTHI + voff + (uint32_t)(g4 * 16 * 2));
        ldsm4(vl, sb + SM_VTLO + voff + (uint32_t)(g4 * 16 * 2));
        #pragma unroll
        for (int mt = 0; mt < 2; ++mt)
            #pragma unroll
            for (int sp = 0; sp < 2; ++sp) {
                mma16816(oacc[mt][sp], ph[mt], vh[2 * sp], vh[2 * sp + 1]);
                mma16816(oacc[mt][sp], ph[mt], vl[2 * sp], vl[2 * sp + 1]);
                mma16816(oacc[mt][sp], pl[mt], vh[2 * sp], vh[2 * sp + 1]);
            }
    }

    // quad-reduce row sums, normalize, store Y into A region
    #pragma unroll
    for (int mt = 0; mt < 2; ++mt)
        #pragma unroll
        for (int h = 0; h < 2; ++h) {
            rsum[mt][h] += __shfl_xor_sync(0xFFFFFFFFu, rsum[mt][h], 1);
            rsum[mt][h] += __shfl_xor_sync(0xFFFFFFFFu, rsum[mt][h], 2);
            rsum[mt][h] = 1.0f / rsum[mt][h];
        }
    #pragma unroll
    for (int mt = 0; mt < 2; ++mt)
        #pragma unroll
        for (int sp = 0; sp < 2; ++sp) {
            int col = head * 16 + sp * 8 + 2 * (lane & 3);
            int r0 = wm * 32 + mt * 16 + (lane >> 2);
            split_pair(smemc + SM_AHI, smemc + SM_ALO, r0, col, AST,
                       oacc[mt][sp][0] * rsum[mt][0], oacc[mt][sp][1] * rsum[mt][0]);
            split_pair(smemc + SM_AHI, smemc + SM_ALO, r0 + 8, col, AST,
                       oacc[mt][sp][2] * rsum[mt][1], oacc[mt][sp][3] * rsum[mt][1]);
        }
    __syncthreads();   // Y tiles ready

    // ---- conv GEMM + scattered output ----
    {
        float acc[2][2][4] = {};
        gemm_tile_g(aHi, aLo, bhC, blC, lane, wm, acc);
        #pragma unroll
        for (int mt = 0; mt < 2; ++mt) {
            int m0 = erow + mt * 16;
            int m1 = m0 + 8;
            int gz0 = z0 + (m0 >> 4), gy0 = y0 + ((m0 >> 2) & 3), gx0 = x0 + (m0 & 3);
            int gz1 = z0 + (m1 >> 4), gy1 = y0 + ((m1 >> 2) & 3), gx1 = x0 + (m1 & 3);
            bool ok0 = (gz0 < D0 && gy0 < H0 && gx0 < W0);
            bool ok1 = (gz1 < D0 && gy1 < H0 && gx1 < W0);
            size_t va0 = (size_t)(gz0 * H0 + gy0) * W0 + gx0;
            size_t va1 = (size_t)(gz1 * H0 + gy1) * W0 + gx1;
            #pragma unroll
            for (int nt = 0; nt < 2; ++nt) {
                int o = ecol + nt * 8;
                float2 cb = *(const float2*)(conv_b + o);
                if (ok0) {
                    out[(size_t)o * MTOT + va0]       = acc[mt][nt][0] + cb.x;
                    out[(size_t)(o + 1) * MTOT + va0] = acc[mt][nt][1] + cb.y;
                }
                if (ok1) {
                    out[(size_t)o * MTOT + va1]       = acc[mt][nt][2] + cb.x;
                    out[(size_t)(o + 1) * MTOT + va1] = acc[mt][nt][3] + cb.y;
                }
            }
        }
    }
}

extern "C" void kernel_launch(void* const* d_in, const int* in_sizes, int n_in,
                              void* d_out, int out_size)
{
    const float* x      = (const float*)d_in[0];
    const float* qkv_w  = (const float*)d_in[1];
    const float* qkv_b  = (const float*)d_in[2];
    const float* conv_w = (const float*)d_in[3];
    const float* conv_b = (const float*)d_in[4];
    float* out = (float*)d_out;

    prep_weights<<<32, 256>>>(qkv_w, conv_w);

    cudaFuncSetAttribute(fused_window_attn_mma,
                         cudaFuncAttributeMaxDynamicSharedMemorySize, SMEM_BYTES);

    fused_window_attn_mma<<<4096, 512, SMEM_BYTES>>>(x, qkv_b, conv_b, out);
}

// round 10
// speedup vs baseline: 2.2746x; 1.4159x over previous
#include <cuda_runtime.h>
#include <cuda_fp16.h>
#include <cstdint>

// Fused 3D windowed attention block — fp16 tensor-core with minimal split terms.
// QKV GEMMs: 2-term (x hi-only, W hi+lo). QK^T: 1-term (q,k hi). PV: 2-term (p hi, V hi+lo).
// conv: 3-term (Y hi+lo, W hi+lo). 1 window/CTA, 512 threads, 2 CTAs/SM.

#define D0 30
#define H0 62
#define W0 126
#define MTOT (30*62*126)

#define AST 136     // halves/row, A & Y tiles (64 rows)
#define KST 136     // halves/row, K hi tile (64 rows)
#define VTST 72     // halves/row, Vt tiles (128 dim rows x 64 keys + pad)

#define SM_AHI  0          // x hi / Y hi
#define SM_ALO  17408      // Y lo (unused during x phase)
#define SM_KHI  34816      // K hi
#define SM_VTHI 52224      // Vt hi
#define SM_VTLO 70656      // Vt lo
#define SM_BIAS 89088      // 384 f32
#define SMEM_BYTES 90624

// weights in B-fragment order: [mat 0..3][wn 0..7][kk 0..7][lane 0..31] x uint4
// mats: 0=Q, 1=K, 2=V, 3=conv
__device__ __align__(256) uint4 g_bh4[4 * 8 * 8 * 32];
__device__ __align__(256) uint4 g_bl4[4 * 8 * 8 * 32];

__device__ __forceinline__ uint32_t smem_u32(const void* p) {
    uint32_t a;
    asm("{ .reg .u64 t; cvta.to.shared.u64 t, %1; cvt.u32.u64 %0, t; }"
        : "=r"(a) : "l"(p));
    return a;
}
__device__ __forceinline__ void ldsm4(uint32_t (&r)[4], uint32_t addr) {
    asm volatile("ldmatrix.sync.aligned.m8n8.x4.shared.b16 {%0,%1,%2,%3}, [%4];"
                 : "=r"(r[0]), "=r"(r[1]), "=r"(r[2]), "=r"(r[3]) : "r"(addr));
}
__device__ __forceinline__ void mma16816(float (&d)[4], const uint32_t (&a)[4],
                                         uint32_t b0, uint32_t b1) {
    asm volatile("mma.sync.aligned.m16n8k16.row.col.f32.f16.f16.f32 "
                 "{%0,%1,%2,%3}, {%4,%5,%6,%7}, {%8,%9}, {%0,%1,%2,%3};"
                 : "+f"(d[0]), "+f"(d[1]), "+f"(d[2]), "+f"(d[3])
                 : "r"(a[0]), "r"(a[1]), "r"(a[2]), "r"(a[3]), "r"(b0), "r"(b1));
}
__device__ __forceinline__ uint32_t h2u(__half a, __half b) {
    __half2 p = __halves2half2(a, b);
    return *(uint32_t*)&p;
}
__device__ __forceinline__ uint32_t packf16(float a, float b) {
    __half2 p = __floats2half2_rn(a, b);
    return *(uint32_t*)&p;
}
__device__ __forceinline__ uint32_t splitf16(float a, float b, uint32_t& lo) {
    __half h0 = __float2half_rn(a), h1 = __float2half_rn(b);
    __half l0 = __float2half_rn(a - __half2float(h0));
    __half l1 = __float2half_rn(b - __half2float(h1));
    lo = h2u(l0, l1);
    return h2u(h0, h1);
}
__device__ __forceinline__ void split_pair(char* hiB, char* loB, int row, int col,
                                           int stride, float v0, float v1) {
    uint32_t lo, hi = splitf16(v0, v1, lo);
    int off = (row * stride + col) * 2;
    *(uint32_t*)(hiB + off) = hi;
    *(uint32_t*)(loB + off) = lo;
}
__device__ __forceinline__ void split1h(char* hiB, char* loB, int off_h, float v) {
    __half h = __float2half_rn(v);
    __half l = __float2half_rn(v - __half2float(h));
    *(__half*)(hiB + 2 * off_h) = h;
    *(__half*)(loB + 2 * off_h) = l;
}

// 32x16x128 warp GEMM, 2-term fp16 (A hi-only): 8 mma/kk
__device__ __forceinline__ void gemm2(uint32_t aHi,
                                      const uint4* __restrict__ bh,
                                      const uint4* __restrict__ bl,
                                      int lane, int wm, float acc[2][2][4]) {
    const int r8 = lane & 7, g = lane >> 3;
    const uint32_t aoff = (uint32_t)(((wm * 32 + r8 + 8 * (g & 1)) * AST + 8 * (g >> 1)) * 2);
    #pragma unroll
    for (int kk = 0; kk < 8; ++kk) {
        uint4 BH = __ldg(bh + kk * 32);
        uint4 BL = __ldg(bl + kk * 32);
        uint32_t ah[2][4];
        #pragma unroll
        for (int mt = 0; mt < 2; ++mt)
            ldsm4(ah[mt], aHi + aoff + (uint32_t)((mt * 16 * AST + kk * 16) * 2));
        #pragma unroll
        for (int mt = 0; mt < 2; ++mt) {
            mma16816(acc[mt][0], ah[mt], BH.x, BH.y);
            mma16816(acc[mt][0], ah[mt], BL.x, BL.y);
            mma16816(acc[mt][1], ah[mt], BH.z, BH.w);
            mma16816(acc[mt][1], ah[mt], BL.z, BL.w);
        }
    }
}

// 32x16x128 warp GEMM, 3-term fp16 (A hi+lo): 12 mma/kk  (conv)
__device__ __forceinline__ void gemm3(uint32_t aHi, uint32_t aLo,
                                      const uint4* __restrict__ bh,
                                      const uint4* __restrict__ bl,
                                      int lane, int wm, float acc[2][2][4]) {
    const int r8 = lane & 7, g = lane >> 3;
    const uint32_t aoff = (uint32_t)(((wm * 32 + r8 + 8 * (g & 1)) * AST + 8 * (g >> 1)) * 2);
    #pragma unroll
    for (int kk = 0; kk < 8; ++kk) {
        uint4 BH = __ldg(bh + kk * 32);
        uint4 BL = __ldg(bl + kk * 32);
        uint32_t ah[2][4], al[2][4];
        #pragma unroll
        for (int mt = 0; mt < 2; ++mt) {
            uint32_t o = aoff + (uint32_t)((mt * 16 * AST + kk * 16) * 2);
            ldsm4(ah[mt], aHi + o);
            ldsm4(al[mt], aLo + o);
        }
        #pragma unroll
        for (int mt = 0; mt < 2; ++mt) {
            mma16816(acc[mt][0], ah[mt], BH.x, BH.y);
            mma16816(acc[mt][0], ah[mt], BL.x, BL.y);
            mma16816(acc[mt][0], al[mt], BH.x, BH.y);
            mma16816(acc[mt][1], ah[mt], BH.z, BH.w);
            mma16816(acc[mt][1], ah[mt], BL.z, BL.w);
            mma16816(acc[mt][1], al[mt], BH.z, BH.w);
        }
    }
}

// ---------------- prep: weights -> fp16 hi/lo B-fragment layout ----------------
__global__ void prep_weights(const float* __restrict__ qkv_w,
                             const float* __restrict__ conv_w)
{
    int tid = blockIdx.x * 256 + threadIdx.x;    // 0..8191
    int lane = tid & 31;
    int kk   = (tid >> 5) & 7;
    int wn   = (tid >> 8) & 7;
    int mat  = tid >> 11;
    const float* W = (mat < 3) ? (qkv_w + mat * 16384) : conv_w;

    uint32_t hi[4], lo[4];
    #pragma unroll
    for (int r = 0; r < 4; ++r) {
        int n = wn * 16 + (r >> 1) * 8 + (lane >> 2);
        int k = kk * 16 + (r & 1) * 8 + 2 * (lane & 3);
        float v0 = W[n * 128 + k];
        float v1 = W[n * 128 + k + 1];
        hi[r] = splitf16(v0, v1, lo[r]);
    }
    g_bh4[tid] = make_uint4(hi[0], hi[1], hi[2], hi[3]);
    g_bl4[tid] = make_uint4(lo[0], lo[1], lo[2], lo[3]);
}

// ---------------- main kernel ----------------
__global__ void __launch_bounds__(512, 2)
fused_window_attn_mma(const float* __restrict__ x,
                      const float* __restrict__ qkv_b,
                      const float* __restrict__ conv_b,
                      float* __restrict__ out)
{
    extern __shared__ char smemc[];
    const uint32_t sb = smem_u32(smemc);
    float* biasS = (float*)(smemc + SM_BIAS);

    const int t    = threadIdx.x;
    const int wid  = t >> 5;
    const int lane = t & 31;
    const int wm = wid >> 3;
    const int wn = wid & 7;
    const int wi = blockIdx.x;
    const int bz = wi >> 9, by = (wi >> 5) & 15, bx = wi & 31;
    const int z0 = bz * 4, y0 = by * 4, x0 = bx * 4;

    // ---- phase 1: gather x -> A hi (fp16), bias ----
    #pragma unroll
    for (int it = 0; it < 8; ++it) {
        int idx = t + 512 * it;
        int l  = idx & 63;
        int cp = idx >> 6;
        int gz = z0 + (l >> 4);
        int gy = y0 + ((l >> 2) & 3);
        int gx = x0 + (l & 3);
        float v0 = 0.f, v1 = 0.f;
        if (gz < D0 && gy < H0 && gx < W0) {
            size_t base = (size_t)(gz * H0 + gy) * W0 + gx;
            v0 = x[(size_t)(2 * cp) * MTOT + base];
            v1 = x[(size_t)(2 * cp + 1) * MTOT + base];
        }
        *(uint32_t*)(smemc + SM_AHI + (l * AST + 2 * cp) * 2) = packf16(v0, v1);
    }
    if (t < 384) biasS[t] = qkv_b[t];
    __syncthreads();

    const uint32_t aHi = sb + SM_AHI, aLo = sb + SM_ALO;
    const int fragbase = wn * 8 * 32 + lane;
    const uint4* bhQ = g_bh4 + 0 * 2048 + fragbase;
    const uint4* blQ = g_bl4 + 0 * 2048 + fragbase;
    const uint4* bhK = g_bh4 + 1 * 2048 + fragbase;
    const uint4* blK = g_bl4 + 1 * 2048 + fragbase;
    const uint4* bhV = g_bh4 + 2 * 2048 + fragbase;
    const uint4* blV = g_bl4 + 2 * 2048 + fragbase;
    const uint4* bhC = g_bh4 + 3 * 2048 + fragbase;
    const uint4* blC = g_bl4 + 3 * 2048 + fragbase;

    const int erow = wm * 32 + (lane >> 2);
    const int ecol = wn * 16 + 2 * (lane & 3);

    // ---- K chunk -> K hi smem ----
    {
        float acc[2][2][4] = {};
        gemm2(aHi, bhK, blK, lane, wm, acc);
        #pragma unroll
        for (int mt = 0; mt < 2; ++mt)
            #pragma unroll
            for (int nt = 0; nt < 2; ++nt) {
                int col = ecol + nt * 8;
                float2 bv = *(const float2*)(biasS + 128 + col);
                int r0 = erow + mt * 16;
                *(uint32_t*)(smemc + SM_KHI + (r0 * KST + col) * 2) =
                    packf16(acc[mt][nt][0] + bv.x, acc[mt][nt][1] + bv.y);
                *(uint32_t*)(smemc + SM_KHI + ((r0 + 8) * KST + col) * 2) =
                    packf16(acc[mt][nt][2] + bv.x, acc[mt][nt][3] + bv.y);
            }
    }

    // ---- V chunk -> Vt hi/lo smem (transposed) ----
    {
        float acc[2][2][4] = {};
        gemm2(aHi, bhV, blV, lane, wm, acc);
        #pragma unroll
        for (int mt = 0; mt < 2; ++mt)
            #pragma unroll
            for (int nt = 0; nt < 2; ++nt) {
                int col = ecol + nt * 8;
                float2 bv = *(const float2*)(biasS + 256 + col);
                int r0 = erow + mt * 16;
                split1h(smemc + SM_VTHI, smemc + SM_VTLO, col * VTST + r0,           acc[mt][nt][0] + bv.x);
                split1h(smemc + SM_VTHI, smemc + SM_VTLO, (col + 1) * VTST + r0,     acc[mt][nt][1] + bv.y);
                split1h(smemc + SM_VTHI, smemc + SM_VTLO, col * VTST + r0 + 8,       acc[mt][nt][2] + bv.x);
                split1h(smemc + SM_VTHI, smemc + SM_VTLO, (col + 1) * VTST + r0 + 8, acc[mt][nt][3] + bv.y);
            }
    }

    // ---- Q chunk (hi fragments stay in registers) ----
    uint32_t qh[2][4];
    {
        float acc[2][2][4] = {};
        gemm2(aHi, bhQ, blQ, lane, wm, acc);
        #pragma unroll
        for (int mt = 0; mt < 2; ++mt)
            #pragma unroll
            for (int nt = 0; nt < 2; ++nt) {
                int col = ecol + nt * 8;
                float2 bv = *(const float2*)(biasS + col);
                qh[mt][2 * nt]     = packf16(acc[mt][nt][0] + bv.x, acc[mt][nt][1] + bv.y);
                qh[mt][2 * nt + 1] = packf16(acc[mt][nt][2] + bv.x, acc[mt][nt][3] + bv.y);
            }
    }
    __syncthreads();   // K/Vt visible; all A reads done

    // ---- attention, warp = (rowhalf wm, head wn) ----
    unsigned long long pm = 0ull;
    if (bz == 7 || by == 15 || bx == 31) {
        #pragma unroll
        for (int m = 0; m < 64; ++m) {
            bool p = (bz == 7 && (m >> 4) >= 2) ||
                     (by == 15 && ((m >> 2) & 3) >= 2) ||
                     (bx == 31 && (m & 3) >= 2);
            pm |= (unsigned long long)(p ? 1u : 0u) << m;
        }
    }
    const int head = wn;
    unsigned rp[2][2];
    #pragma unroll
    for (int mt = 0; mt < 2; ++mt) {
        int r0 = wm * 32 + mt * 16 + (lane >> 2);
        rp[mt][0] = (unsigned)(pm >> r0) & 1u;
        rp[mt][1] = (unsigned)(pm >> (r0 + 8)) & 1u;
    }

    const int r8 = lane & 7;
    const uint32_t koff = (uint32_t)(((r8 + 8 * ((lane >> 4) & 1)) * KST
                                      + head * 16 + 8 * ((lane >> 3) & 1)) * 2);
    const uint32_t voff = (uint32_t)(((head * 16 + r8 + 8 * ((lane >> 4) & 1)) * VTST
                                      + 8 * ((lane >> 3) & 1)) * 2);

    float oacc[2][2][4] = {};
    float rsum[2][2] = {};

    #pragma unroll
    for (int g4 = 0; g4 < 4; ++g4) {
        uint32_t kh[4];
        ldsm4(kh, sb + SM_KHI + koff + (uint32_t)(g4 * 16 * KST * 2));

        float sacc[2][2][4] = {};
        #pragma unroll
        for (int mt = 0; mt < 2; ++mt)
            #pragma unroll
            for (int s = 0; s < 2; ++s)
                mma16816(sacc[mt][s], qh[mt], kh[2 * s], kh[2 * s + 1]);

        uint32_t ph[2][4];
        #pragma unroll
        for (int s = 0; s < 2; ++s) {
            int k0 = g4 * 16 + s * 8 + 2 * (lane & 3);
            unsigned cp0 = (unsigned)(pm >> k0) & 1u;
            unsigned cp1 = (unsigned)(pm >> (k0 + 1)) & 1u;
            #pragma unroll
            for (int mt = 0; mt < 2; ++mt) {
                float e0 = (cp0 == rp[mt][0]) ? __expf(0.25f * sacc[mt][s][0]) : 0.f;
                float e1 = (cp1 == rp[mt][0]) ? __expf(0.25f * sacc[mt][s][1]) : 0.f;
                float e2 = (cp0 == rp[mt][1]) ? __expf(0.25f * sacc[mt][s][2]) : 0.f;
                float e3 = (cp1 == rp[mt][1]) ? __expf(0.25f * sacc[mt][s][3]) : 0.f;
                rsum[mt][0] += e0 + e1;
                rsum[mt][1] += e2 + e3;
                ph[mt][2 * s]     = packf16(e0, e1);
                ph[mt][2 * s + 1] = packf16(e2, e3);
            }
        }

        uint32_t vh[4], vl[4];
        ldsm4(vh, sb + SM_VTHI + voff + (uint32_t)(g4 * 16 * 2));
        ldsm4(vl, sb + SM_VTLO + voff + (uint32_t)(g4 * 16 * 2));
        #pragma unroll
        for (int mt = 0; mt < 2; ++mt)
            #pragma unroll
            for (int sp = 0; sp < 2; ++sp) {
                mma16816(oacc[mt][sp], ph[mt], vh[2 * sp], vh[2 * sp + 1]);
                mma16816(oacc[mt][sp], ph[mt], vl[2 * sp], vl[2 * sp + 1]);
            }
    }

    // quad-reduce row sums, normalize, store Y (hi/lo) into A region
    #pragma unroll
    for (int mt = 0; mt < 2; ++mt)
        #pragma unroll
        for (int h = 0; h < 2; ++h) {
            rsum[mt][h] += __shfl_xor_sync(0xFFFFFFFFu, rsum[mt][h], 1);
            rsum[mt][h] += __shfl_xor_sync(0xFFFFFFFFu, rsum[mt][h], 2);
            rsum[mt][h] = 1.0f / rsum[mt][h];
        }
    #pragma unroll
    for (int mt = 0; mt < 2; ++mt)
        #pragma unroll
        for (int sp = 0; sp < 2; ++sp) {
            int col = head * 16 + sp * 8 + 2 * (lane & 3);
            int r0 = wm * 32 + mt * 16 + (lane >> 2);
            split_pair(smemc + SM_AHI, smemc + SM_ALO, r0, col, AST,
                       oacc[mt][sp][0] * rsum[mt][0], oacc[mt][sp][1] * rsum[mt][0]);
            split_pair(smemc + SM_AHI, smemc + SM_ALO, r0 + 8, col, AST,
                       oacc[mt][sp][2] * rsum[mt][1], oacc[mt][sp][3] * rsum[mt][1]);
        }
    __syncthreads();   // Y tiles ready

    // ---- conv GEMM (3-term) + scattered output ----
    {
        float acc[2][2][4] = {};
        gemm3(aHi, aLo, bhC, blC, lane, wm, acc);
        #pragma unroll
        for (int mt = 0; mt < 2; ++mt) {
            int m0 = erow + mt * 16;
            int m1 = m0 + 8;
            int gz0 = z0 + (m0 >> 4), gy0 = y0 + ((m0 >> 2) & 3), gx0 = x0 + (m0 & 3);
            int gz1 = z0 + (m1 >> 4), gy1 = y0 + ((m1 >> 2) & 3), gx1 = x0 + (m1 & 3);
            bool ok0 = (gz0 < D0 && gy0 < H0 && gx0 < W0);
            bool ok1 = (gz1 < D0 && gy1 < H0 && gx1 < W0);
            size_t va0 = (size_t)(gz0 * H0 + gy0) * W0 + gx0;
            size_t va1 = (size_t)(gz1 * H0 + gy1) * W0 + gx1;
            #pragma unroll
            for (int nt = 0; nt < 2; ++nt) {
                int o = ecol + nt * 8;
                float2 cb = *(const float2*)(conv_b + o);
                if (ok0) {
                    out[(size_t)o * MTOT + va0]       = acc[mt][nt][0] + cb.x;
                    out[(size_t)(o + 1) * MTOT + va0] = acc[mt][nt][1] + cb.y;
                }
                if (ok1) {
                    out[(size_t)o * MTOT + va1]       = acc[mt][nt][2] + cb.x;
                    out[(size_t)(o + 1) * MTOT + va1] = acc[mt][nt][3] + cb.y;
                }
            }
        }
    }
}

extern "C" void kernel_launch(void* const* d_in, const int* in_sizes, int n_in,
                              void* d_out, int out_size)
{
    const float* x      = (const float*)d_in[0];
    const float* qkv_w  = (const float*)d_in[1];
    const float* qkv_b  = (const float*)d_in[2];
    const float* conv_w = (const float*)d_in[3];
    const float* conv_b = (const float*)d_in[4];
    float* out = (float*)d_out;

    prep_weights<<<32, 256>>>(qkv_w, conv_w);

    cudaFuncSetAttribute(fused_window_attn_mma,
                         cudaFuncAttributeMaxDynamicSharedMemorySize, SMEM_BYTES);

    fused_window_attn_mma<<<4096, 512, SMEM_BYTES>>>(x, qkv_b, conv_b, out);
}